// round 7
// baseline (speedup 1.0000x reference)
#include <cuda_runtime.h>

#define H 64
#define B 16
#define L 512
#define TOK_PER_BLOCK 8
#define TOKENS_PER_BATCH (2 * L)                              // 1024
#define CHUNKS_PER_BATCH (TOKENS_PER_BATCH / TOK_PER_BLOCK)   // 128
#define NBLOCKS (B * CHUNKS_PER_BATCH)                        // 2048

// Zero-initialized device globals. The last block restores them to zero at the
// end of every launch, so each graph replay starts from the same state.
__device__ float        g_h[B * H];
__device__ unsigned int g_count;

// ---------------------------------------------------------------------------
// Fused kernel: streaming embedding-gather reduction + last-block MLP tail.
// One block = one batch b, 8 tokens, 256 threads.
// Thread layout: c4 = t & 15  -> float4 column (h = c4*4 .. c4*4+3)
//                wg = t >> 4  -> row group; rows w = wg + 16*it, it=0..3
// Token indices preloaded to smem (no dependent scalar loads in mainloop);
// 2 tokens in flight -> 8 front-batched LDG.128 per thread.
// ---------------------------------------------------------------------------
__global__ void __launch_bounds__(256, 4) fused_kernel(
    const int* __restrict__ s1, const int* __restrict__ s2,
    const float* __restrict__ embed, const float* __restrict__ sos_g,
    const float* __restrict__ w1, const float* __restrict__ b1,
    const float* __restrict__ w2, const float* __restrict__ b2,
    float* __restrict__ out)
{
    __shared__ float s_sos[H];
    __shared__ float s_red[H];
    __shared__ int   s_tok[TOK_PER_BLOCK];
    __shared__ unsigned int s_is_last;

    const int t     = threadIdx.x;
    const int blk   = blockIdx.x;
    const int b     = blk / CHUNKS_PER_BATCH;
    const int chunk = blk % CHUNKS_PER_BATCH;
    const int tok0  = chunk * TOK_PER_BLOCK;       // in [0, 1024)

    if (t < H) { s_sos[t] = sos_g[t]; s_red[t] = 0.0f; }
    if (t < TOK_PER_BLOCK) {
        const int ti = tok0 + t;
        s_tok[t] = (ti < L) ? s1[b * L + ti] : s2[b * L + (ti - L)];
    }
    __syncthreads();

    const int c4 = t & 15;    // float4 column index
    const int wg = t >> 4;    // row group 0..15

    float acc0 = 0.f, acc1 = 0.f, acc2 = 0.f, acc3 = 0.f;

    #pragma unroll
    for (int k = 0; k < TOK_PER_BLOCK; k += 2) {
        const float4* E0 = (const float4*)(embed) + (size_t)s_tok[k]     * (H * H / 4);
        const float4* E1 = (const float4*)(embed) + (size_t)s_tok[k + 1] * (H * H / 4);

        float4 v0[4], v1[4];
        #pragma unroll
        for (int it = 0; it < 4; ++it)
            v0[it] = __ldg(&E0[(wg + 16 * it) * 16 + c4]);
        #pragma unroll
        for (int it = 0; it < 4; ++it)
            v1[it] = __ldg(&E1[(wg + 16 * it) * 16 + c4]);

        #pragma unroll
        for (int it = 0; it < 4; ++it) {
            const float sw = s_sos[wg + 16 * it];
            acc0 = fmaf(sw, v0[it].x, acc0);
            acc1 = fmaf(sw, v0[it].y, acc1);
            acc2 = fmaf(sw, v0[it].z, acc2);
            acc3 = fmaf(sw, v0[it].w, acc3);
        }
        #pragma unroll
        for (int it = 0; it < 4; ++it) {
            const float sw = s_sos[wg + 16 * it];
            acc0 = fmaf(sw, v1[it].x, acc0);
            acc1 = fmaf(sw, v1[it].y, acc1);
            acc2 = fmaf(sw, v1[it].z, acc2);
            acc3 = fmaf(sw, v1[it].w, acc3);
        }
    }

    // Fold lanes l and l+16 (same c4, adjacent row-groups) inside each warp.
    acc0 += __shfl_xor_sync(0xffffffffu, acc0, 16);
    acc1 += __shfl_xor_sync(0xffffffffu, acc1, 16);
    acc2 += __shfl_xor_sync(0xffffffffu, acc2, 16);
    acc3 += __shfl_xor_sync(0xffffffffu, acc3, 16);

    // 8 remaining row-group partials per h -> shared atomics (spread addrs).
    if ((t & 31) < 16) {
        const int hb = c4 * 4;
        atomicAdd(&s_red[hb + 0], acc0);
        atomicAdd(&s_red[hb + 1], acc1);
        atomicAdd(&s_red[hb + 2], acc2);
        atomicAdd(&s_red[hb + 3], acc3);
    }
    __syncthreads();

    // Accumulate block partial into global h (REDG, no return value used).
    if (t < H) atomicAdd(&g_h[b * H + t], s_red[t]);

    // --- last-block-done detection (threadFenceReduction pattern) ---
    __threadfence();
    __syncthreads();
    if (t == 0) {
        const unsigned int prev = atomicAdd(&g_count, 1u);
        s_is_last = (prev == (unsigned int)(NBLOCKS - 1)) ? 1u : 0u;
    }
    __syncthreads();
    if (!s_is_last) return;

    // ===================== last block: MLP tail =====================
    __threadfence();  // acquire: make all blocks' g_h adds visible

    __shared__ float s_hv[B * H];
    #pragma unroll
    for (int i = t; i < B * H; i += 256)
        s_hv[i] = __ldcg(&g_h[i]);   // L2-coherent load (bypass L1)
    __syncthreads();

    // Reset globals for the next graph replay.
    #pragma unroll
    for (int i = t; i < B * H; i += 256)
        g_h[i] = 0.0f;
    if (t == 0) g_count = 0u;

    // 8 warps; warp w handles batches w and w+8.
    const int warp = t >> 5;
    const int lane = t & 31;
    #pragma unroll
    for (int bb = warp; bb < B; bb += 8) {
        const float* hv = s_hv + bb * H;
        float x0 = b1[lane];
        float x1 = b1[lane + 32];
        #pragma unroll
        for (int k = 0; k < H; ++k) {
            const float hk = hv[k];
            x0 = fmaf(hk, w1[lane * H + k],        x0);
            x1 = fmaf(hk, w1[(lane + 32) * H + k], x1);
        }
        x0 = fmaxf(x0, 0.0f);
        x1 = fmaxf(x1, 0.0f);

        float o0 = x0 * w2[lane]     + x1 * w2[lane + 32];
        float o1 = x0 * w2[H + lane] + x1 * w2[H + lane + 32];
        #pragma unroll
        for (int off = 16; off > 0; off >>= 1) {
            o0 += __shfl_xor_sync(0xffffffffu, o0, off);
            o1 += __shfl_xor_sync(0xffffffffu, o1, off);
        }
        if (lane == 0) {
            out[bb * 2 + 0] = o0 + b2[0];
            out[bb * 2 + 1] = o1 + b2[1];
        }
    }
}

extern "C" void kernel_launch(void* const* d_in, const int* in_sizes, int n_in,
                              void* d_out, int out_size) {
    const int*   s1    = (const int*)  d_in[0];
    const int*   s2    = (const int*)  d_in[1];
    const float* embed = (const float*)d_in[2];
    const float* sos   = (const float*)d_in[3];
    const float* w1    = (const float*)d_in[4];
    const float* b1    = (const float*)d_in[5];
    const float* w2    = (const float*)d_in[6];
    const float* b2    = (const float*)d_in[7];
    float* out = (float*)d_out;

    fused_kernel<<<NBLOCKS, 256>>>(s1, s2, embed, sos, w1, b1, w2, b2, out);
}